// round 16
// baseline (speedup 1.0000x reference)
#include <cuda_runtime.h>
#include <cstdint>

#define NN 50000
#define NE 800000
#define NB 64

// ---------------- scratch (device globals: allocation-free) ----------------
__device__ __align__(16) float g_node[NN * 32];
__device__ __align__(16) float g_P[NN * 32];
__device__ __align__(16) float g_Q[NN * 32];
__device__ __align__(16) float g_pvc[NN * 32];
__device__ __align__(16) float g_a[NN * 32];
__device__ __align__(16) float g_Wf[96 * 32];   // Wih @ W3 (fused)
__device__ float g_bf[96];                       // Wih @ b3
__device__ int   g_cnt[NN];     // zero-init at load; re-zeroed by scan_lb each run
__device__ int   g_off[NN + 1];
__device__ int   g_cur[NN];
__device__ int   g_csr[2 * NE];
__device__ int   g_bsum[NB];
__device__ int   g_bflag[NB];   // lookback flags; reset by scatter_embed each run

// ---------------- helpers ----------------
__device__ __forceinline__ uint32_t tf32c(float x) {
    uint32_t r;
    asm("cvt.rna.tf32.f32 %0, %1;" : "=r"(r) : "f"(x));
    return r;
}
__device__ __forceinline__ void mma_tf32(float& d0, float& d1, float& d2, float& d3,
                                         uint32_t a0, uint32_t a1, uint32_t a2, uint32_t a3,
                                         uint32_t b0, uint32_t b1) {
    asm("mma.sync.aligned.m16n8k8.row.col.f32.tf32.tf32.f32 "
        "{%0,%1,%2,%3}, {%4,%5,%6,%7}, {%8,%9}, {%0,%1,%2,%3};"
        : "+f"(d0), "+f"(d1), "+f"(d2), "+f"(d3)
        : "r"(a0), "r"(a1), "r"(a2), "r"(a3), "r"(b0), "r"(b1));
}
__device__ __forceinline__ float sigf(float x) {
    return __fdividef(1.f, 1.f + __expf(-x));
}
__device__ __forceinline__ float tanhfast(float x) {
    float ex = __expf(2.f * x);
    return 1.f - __fdividef(2.f, ex + 1.f);
}
__device__ __forceinline__ void cpasync16(uint32_t dst_s, const void* src) {
    asm volatile("cp.async.cg.shared.global [%0], [%1], 16;"
                 :: "r"(dst_s), "l"(src));
}
__device__ __forceinline__ void cpasync_commit() {
    asm volatile("cp.async.commit_group;" ::: "memory");
}
__device__ __forceinline__ void cpasync_wait0() {
    asm volatile("cp.async.wait_group 0;" ::: "memory");
}
__device__ __forceinline__ void cpasync_wait1() {
    asm volatile("cp.async.wait_group 1;" ::: "memory");
}

// 4 n-tiles x 4 k-steps MMA on a prebuilt A-fragment; accumulate relu into acc
__device__ __forceinline__ void mma_acc(const uint32_t* a,
                                        const uint32_t* B0, const uint32_t* B1,
                                        const float* b2e, const float* b2o,
                                        float* acc) {
#pragma unroll
    for (int nt = 0; nt < 4; nt++) {
        float d0 = 0.f, d1 = 0.f, d2 = 0.f, d3 = 0.f;
#pragma unroll
        for (int kt = 0; kt < 4; kt++)
            mma_tf32(d0, d1, d2, d3,
                     a[kt * 4 + 0], a[kt * 4 + 1], a[kt * 4 + 2], a[kt * 4 + 3],
                     B0[kt * 4 + nt], B1[kt * 4 + nt]);
        acc[nt * 2 + 0] += fmaxf(d0 + b2e[nt], 0.f) + fmaxf(d2 + b2e[nt], 0.f);
        acc[nt * 2 + 1] += fmaxf(d1 + b2o[nt], 0.f) + fmaxf(d3 + b2o[nt], 0.f);
    }
}

// Build A-fragment a[16] directly from the staged (XOR-swizzled) smem buffer.
// Derived from the round-8-verified mapping:
//   a[T] = h1[row = (j>>2) + 8*(T&1) + tb][col = 4*(T>>1) + (j&3)]
// Staged word for (row,col) = row*32 + 4*((col>>2) ^ (row&7)) + (col&3),
// and (row&7) == j>>2 for every row this lane touches -> immediate offsets.
__device__ __forceinline__ void build_tile_staged(uint32_t* a, const float* stg,
                                                  int tb, int cnt,
                                                  const float* p8, int j) {
    int jq = j >> 2;
    const float* base = stg + (jq + tb) * 32 + (j & 3);
#pragma unroll
    for (int T = 0; T < 16; T++) {
        int g = T >> 1, rowhi = T & 1;
        int row = jq + 8 * rowhi + tb;
        float qv = base[256 * rowhi + 4 * (g ^ jq)];
        float h = (row < cnt) ? fmaxf(p8[g] + qv, 0.f) : 0.f;
        a[T] = tf32c(h);
    }
}

// Build A-fragment directly from global Q rows (later chunks).
__device__ __forceinline__ void build_tile_direct(uint32_t* a, int vd, int tb,
                                                  int cnt, const float* p8,
                                                  int j) {
    int jq = j >> 2;
    int r0 = jq + tb;
    int v0 = __shfl_sync(0xffffffffu, vd, r0);
    int v1 = __shfl_sync(0xffffffffu, vd, r0 + 8);
    const float* q0 = &g_Q[(size_t)v0 * 32 + (j & 3)];
    const float* q1 = &g_Q[(size_t)v1 * 32 + (j & 3)];
#pragma unroll
    for (int T = 0; T < 16; T++) {
        int g = T >> 1, rowhi = T & 1;
        int row = r0 + 8 * rowhi;
        float qv = (rowhi ? q1 : q0)[4 * g];
        float h = (row < cnt) ? fmaxf(p8[g] + qv, 0.f) : 0.f;
        a[T] = tf32c(h);
    }
}

// ---------------- prep kernel 1: degree count ----------------
__global__ void count_kernel(const int* __restrict__ e, int n2e) {
    int i = blockIdx.x * blockDim.x + threadIdx.x;
    if (i < n2e) atomicAdd(&g_cnt[e[i]], 1);
}

// ---------------- prep kernel 2: decoupled-lookback scan + wf ----------
__global__ void scan_lb_kernel(const float* __restrict__ Wih,
                               const float* __restrict__ W3,
                               const float* __restrict__ b3,
                               int n, int seg) {
    int b = blockIdx.x, tid = threadIdx.x;
    if (b == NB) {   // fused wf
        for (int idx = tid; idx < 96 * 32; idx += 256) {
            int g = idx >> 5, k = idx & 31;
            float s = 0.f;
#pragma unroll
            for (int o = 0; o < 32; o++)
                s = fmaf(Wih[g * 32 + o], W3[o * 32 + k], s);
            g_Wf[idx] = s;
        }
        if (tid < 96) {
            float s = 0.f;
#pragma unroll
            for (int o = 0; o < 32; o++)
                s = fmaf(Wih[tid * 32 + o], b3[o], s);
            g_bf[tid] = s;
        }
        return;
    }

    int beg = b * seg, end = min(beg + seg, n);
    int len = max(end - beg, 0);
    int c = (len + 255) / 256;
    int tb = min(beg + tid * c, end), te = min(tb + c, end);
    int s = 0;
    for (int i = tb; i < te; i++) s += g_cnt[i];
    int lane = tid & 31, w = tid >> 5;
    int v = s;
#pragma unroll
    for (int o = 1; o < 32; o <<= 1) {
        int t = __shfl_up_sync(0xffffffffu, v, o);
        if (lane >= o) v += t;
    }
    __shared__ int wt[8], wpre[8];
    __shared__ int s_pre;
    if (lane == 31) wt[w] = v;
    if (tid == 0) s_pre = 0;
    __syncthreads();
    if (tid < 8) {
        int x = wt[tid];
#pragma unroll
        for (int o = 1; o < 8; o <<= 1) {
            int t = __shfl_up_sync(0xffu, x, o);
            if (tid >= o) x += t;
        }
        wpre[tid] = x;
    }
    __syncthreads();

    if (tid == 0) {
        g_bsum[b] = wpre[7];
        __threadfence();
        atomicExch(&g_bflag[b], 1);
    }
    if (tid < b) {
        while (atomicAdd(&g_bflag[tid], 0) == 0) {}
        __threadfence();
        atomicAdd(&s_pre, g_bsum[tid]);
    }
    __syncthreads();

    int excl = (v - s) + (w > 0 ? wpre[w - 1] : 0);
    int run = s_pre + excl;
    for (int i = tb; i < te; i++) {
        g_off[i] = run;
        g_cur[i] = run;
        run += g_cnt[i];
    }
    for (int i = tb; i < te; i++) g_cnt[i] = 0;
    if (b == NB - 1 && tid == 255) g_off[n] = run;
}

// ---------------- prep kernel 3: scatter + embed (fused) ----------
__global__ void scatter_embed_kernel(const int* __restrict__ e, int nE,
                                     const float* __restrict__ classes,
                                     const float* __restrict__ pos,
                                     const float* __restrict__ Win,
                                     const float* __restrict__ bin,
                                     const float* __restrict__ W1,
                                     const float* __restrict__ b1,
                                     int n_nodes, int nsb) {
    if (blockIdx.x == 0 && threadIdx.x < NB) g_bflag[threadIdx.x] = 0;

    if (blockIdx.x < nsb) {
        int i = blockIdx.x * blockDim.x + threadIdx.x;
        if (i >= 2 * nE) return;
        int src = e[i];
        int dst = (i < nE) ? e[i + nE] : e[i - nE];
        int slot = atomicAdd(&g_cur[src], 1);
        g_csr[slot] = dst;
        return;
    }

    int warp = ((blockIdx.x - nsb) * blockDim.x + threadIdx.x) >> 5;
    int j = threadIdx.x & 31;
    if (warp >= n_nodes) return;
    int u = warp;

    float w[16];
#pragma unroll
    for (int k = 0; k < 16; k++) w[k] = Win[j * 16 + k];
    float c = (j < 16) ? classes[u * 16 + j] : 0.f;
    float acc = bin[j];
#pragma unroll
    for (int k = 0; k < 16; k++)
        acc = fmaf(w[k], __shfl_sync(0xffffffffu, c, k), acc);
    g_node[u * 32 + j] = acc;

    float p0 = pos[u * 3 + 0], p1 = pos[u * 3 + 1], p2 = pos[u * 3 + 2];
    float pv = p0 * W1[j * 67 + 64] + p1 * W1[j * 67 + 65] + p2 * W1[j * 67 + 66];
    g_pvc[u * 32 + j] = pv;

    float p = 0.f, q = 0.f;
#pragma unroll
    for (int k = 0; k < 32; k++) {
        float val = __shfl_sync(0xffffffffu, acc, k);
        p = fmaf(W1[j * 67 + k], val, p);
        q = fmaf(W1[j * 67 + 32 + k], val, q);
    }
    g_P[u * 32 + j] = p + b1[j] - pv;
    g_Q[u * 32 + j] = q + pv;
}

// ---------------- message-pass kernel: direct fragment build ----------
// smem per warp: 2 stage buffers of 1024 floats (XOR-swizzled raw Q rows).
// No fragment smem; no STS in the hot path. 3 blocks/SM (64KB each).
#define EDGE_SMEM_BYTES (8 * 2048 * 4)

__global__ void __launch_bounds__(256, 3) edge_kernel(
        const float* __restrict__ W2, const float* __restrict__ b2,
        int n_nodes) {
    extern __shared__ float sm[];
    int tid = threadIdx.x, wl = tid >> 5, j = tid & 31;

    uint32_t B0[16], B1[16];
#pragma unroll
    for (int kt = 0; kt < 4; kt++)
#pragma unroll
        for (int nt = 0; nt < 4; nt++) {
            int ncol = nt * 8 + (j >> 2);
            int krow = kt * 8 + (j & 3);
            B0[kt * 4 + nt] = tf32c(W2[ncol * 32 + krow]);
            B1[kt * 4 + nt] = tf32c(W2[ncol * 32 + krow + 4]);
        }
    float b2e[4], b2o[4];
#pragma unroll
    for (int nt = 0; nt < 4; nt++) {
        b2e[nt] = b2[nt * 8 + (j & 3) * 2];
        b2o[nt] = b2[nt * 8 + (j & 3) * 2 + 1];
    }
    float bb2 = b2[j];

    float* stage = sm + wl * 2048;   // buf b at + b*1024

    int jc = j & 7;            // staging col group
    int jr = j >> 3;           // staging row residue
    int nw = gridDim.x * 8;

    int u = blockIdx.x * 8 + wl;
    int s = 0, e = 0;
    float pj = 0.f;
    int s2 = 0, e2 = 0;
    float pj2 = 0.f;

    if (u < n_nodes) {
        s = g_off[u]; e = g_off[u + 1];
        pj = g_P[(size_t)u * 32 + j];
        int vc = (s + j < e) ? g_csr[s + j] : 0;
        int cnt0 = min(32, e - s);
#pragma unroll
        for (int k = 0; k < 8; k++) {
            int row = jr + 4 * k;
            int vv = __shfl_sync(0xffffffffu, vc, row);
            if (row < cnt0) {
                uint32_t d = (uint32_t)__cvta_generic_to_shared(
                    stage + row * 32 + ((jc ^ (row & 7)) << 2));
                cpasync16(d, &g_Q[(size_t)vv * 32 + jc * 4]);
            }
        }
        cpasync_commit();
        int u2 = u + nw;
        if (u2 < n_nodes) {
            s2 = g_off[u2]; e2 = g_off[u2 + 1];
            pj2 = g_P[(size_t)u2 * 32 + j];
        }
    }

    int ib = 0;
    for (; u < n_nodes; u += nw, ib ^= 1) {
        int u2 = u + nw;
        if (u2 < n_nodes) {
            int vc2 = (s2 + j < e2) ? g_csr[s2 + j] : 0;
            float* stg1 = stage + (ib ^ 1) * 1024;
            int cnt0 = min(32, e2 - s2);
#pragma unroll
            for (int k = 0; k < 8; k++) {
                int row = jr + 4 * k;
                int vv = __shfl_sync(0xffffffffu, vc2, row);
                if (row < cnt0) {
                    uint32_t d = (uint32_t)__cvta_generic_to_shared(
                        stg1 + row * 32 + ((jc ^ (row & 7)) << 2));
                    cpasync16(d, &g_Q[(size_t)vv * 32 + jc * 4]);
                }
            }
            cpasync_commit();
        }
        int u3 = u + 2 * nw;
        int s3 = 0, e3 = 0;
        float pj3 = 0.f;
        if (u3 < n_nodes) {
            s3 = g_off[u3]; e3 = g_off[u3 + 1];
            pj3 = g_P[(size_t)u3 * 32 + j];
        }
        if (u2 < n_nodes) cpasync_wait1(); else cpasync_wait0();
        __syncwarp();

        // P values at the 8 columns this lane's fragments need
        float p8[8];
#pragma unroll
        for (int g = 0; g < 8; g++)
            p8[g] = __shfl_sync(0xffffffffu, pj, 4 * g + (j & 3));

        float acc[8];
#pragma unroll
        for (int r = 0; r < 8; r++) acc[r] = 0.f;

        int deg = e - s;
        float* stg = stage + ib * 1024;
        int vd = (s + 32 + j < e) ? g_csr[s + 32 + j] : 0;

        if (deg > 0) {
            int cnt = min(32, deg);
            {
                uint32_t a[16];
                build_tile_staged(a, stg, 0, cnt, p8, j);
                mma_acc(a, B0, B1, b2e, b2o, acc);
            }
            if (cnt > 16) {
                uint32_t a[16];
                build_tile_staged(a, stg, 16, cnt, p8, j);
                mma_acc(a, B0, B1, b2e, b2o, acc);
            }

            for (int base = s + 32; base < e; base += 32) {
                int cnt2 = min(32, e - base);
                int vdn = (base + 32 + j < e) ? g_csr[base + 32 + j] : 0;
                {
                    uint32_t a[16];
                    build_tile_direct(a, vd, 0, cnt2, p8, j);
                    mma_acc(a, B0, B1, b2e, b2o, acc);
                }
                if (cnt2 > 16) {
                    uint32_t a[16];
                    build_tile_direct(a, vd, 16, cnt2, p8, j);
                    mma_acc(a, B0, B1, b2e, b2o, acc);
                }
                vd = vdn;
            }
        }

        // cross-lane reduce + remap to col-per-lane (layout verified round 8)
#pragma unroll
        for (int o = 4; o < 32; o <<= 1)
#pragma unroll
            for (int r = 0; r < 8; r++)
                acc[r] += __shfl_xor_sync(0xffffffffu, acc[r], o);
        __syncwarp();
#pragma unroll
        for (int r = 0; r < 8; r++) stg[r * 32 + j] = acc[r];
        __syncwarp();
        float accj = stg[(((j >> 3) << 1) + (j & 1)) * 32 + ((j & 7) >> 1)];

        int pad = ((deg + 15) & ~15) - deg;
        accj -= (float)pad * fmaxf(bb2, 0.f);

        g_a[(size_t)u * 32 + j] = accj;
        __syncwarp();   // stg reuse fence before next iteration's staging

        s = s2; e = e2; pj = pj2;
        s2 = s3; e2 = e3; pj2 = pj3;
    }
}

// ---------------- fused epilogue: node-per-thread (round-14) ----------
__global__ void __launch_bounds__(352, 1) gru_kernel(
        const float* __restrict__ W1, const float* __restrict__ b1,
        const float* __restrict__ Whh,
        const float* __restrict__ bih, const float* __restrict__ bhh,
        float* __restrict__ out, int write_pq, int n_nodes) {
    __shared__ float sWf[96 * 32];
    __shared__ float sWhh[96 * 32];
    __shared__ float sW1[64 * 32];
    __shared__ float sbi[96], sbf[96], sbhh[96], sb1[32];
    int tid = threadIdx.x;
    for (int i = tid; i < 96 * 32; i += 352) { sWf[i] = g_Wf[i]; sWhh[i] = Whh[i]; }
    for (int i = tid; i < 32 * 32; i += 352) {
        sW1[i] = W1[(i >> 5) * 67 + (i & 31)];
        sW1[1024 + i] = W1[(i >> 5) * 67 + 32 + (i & 31)];
    }
    if (tid < 96) { sbi[tid] = bih[tid]; sbf[tid] = g_bf[tid]; sbhh[tid] = bhh[tid]; }
    if (tid < 32) sb1[tid] = b1[tid];
    __syncthreads();

    int u = blockIdx.x * 352 + tid;
    if (u >= n_nodes) return;

    float S[32];
    {
        const float4* Sg = (const float4*)&g_a[(size_t)u * 32];
#pragma unroll
        for (int c = 0; c < 8; c++) {
            float4 v = Sg[c];
            S[c * 4] = v.x; S[c * 4 + 1] = v.y; S[c * 4 + 2] = v.z; S[c * 4 + 3] = v.w;
        }
    }
    float deg = (float)(g_off[u + 1] - g_off[u]);

    float h[32];
    {
        const float4* Hg = (const float4*)&g_node[(size_t)u * 32];
#pragma unroll
        for (int c = 0; c < 8; c++) {
            float4 v = Hg[c];
            h[c * 4] = v.x; h[c * 4 + 1] = v.y; h[c * 4 + 2] = v.z; h[c * 4 + 3] = v.w;
        }
    }

    float nh[32];
    for (int o = 0; o < 32; o++) {
        const float4* wr = (const float4*)&sWf[o * 32];
        const float4* wz = (const float4*)&sWf[(o + 32) * 32];
        const float4* wn = (const float4*)&sWf[(o + 64) * 32];
        const float4* vr = (const float4*)&sWhh[o * 32];
        const float4* vz = (const float4*)&sWhh[(o + 32) * 32];
        const float4* vn = (const float4*)&sWhh[(o + 64) * 32];
        float gir = fmaf(deg, sbf[o],      sbi[o]);
        float giz = fmaf(deg, sbf[o + 32], sbi[o + 32]);
        float gin = fmaf(deg, sbf[o + 64], sbi[o + 64]);
        float ghr = sbhh[o], ghz = sbhh[o + 32], ghn = sbhh[o + 64];
#pragma unroll
        for (int c = 0; c < 8; c++) {
            float a0 = S[4 * c], a1 = S[4 * c + 1], a2 = S[4 * c + 2], a3 = S[4 * c + 3];
            float h0 = h[4 * c], h1 = h[4 * c + 1], h2 = h[4 * c + 2], h3 = h[4 * c + 3];
            float4 w;
            w = wr[c]; gir = fmaf(w.x, a0, gir); gir = fmaf(w.y, a1, gir);
                       gir = fmaf(w.z, a2, gir); gir = fmaf(w.w, a3, gir);
            w = wz[c]; giz = fmaf(w.x, a0, giz); giz = fmaf(w.y, a1, giz);
                       giz = fmaf(w.z, a2, giz); giz = fmaf(w.w, a3, giz);
            w = wn[c]; gin = fmaf(w.x, a0, gin); gin = fmaf(w.y, a1, gin);
                       gin = fmaf(w.z, a2, gin); gin = fmaf(w.w, a3, gin);
            w = vr[c]; ghr = fmaf(w.x, h0, ghr); ghr = fmaf(w.y, h1, ghr);
                       ghr = fmaf(w.z, h2, ghr); ghr = fmaf(w.w, h3, ghr);
            w = vz[c]; ghz = fmaf(w.x, h0, ghz); ghz = fmaf(w.y, h1, ghz);
                       ghz = fmaf(w.z, h2, ghz); ghz = fmaf(w.w, h3, ghz);
            w = vn[c]; ghn = fmaf(w.x, h0, ghn); ghn = fmaf(w.y, h1, ghn);
                       ghn = fmaf(w.z, h2, ghn); ghn = fmaf(w.w, h3, ghn);
        }
        float r = sigf(gir + ghr);
        float z = sigf(giz + ghz);
        float nv = tanhfast(gin + r * ghn);
        nh[o] = (1.f - z) * nv + z * h[o];
    }

    {
        float4* Ng = (float4*)&g_node[(size_t)u * 32];
#pragma unroll
        for (int c = 0; c < 8; c++)
            Ng[c] = make_float4(nh[4 * c], nh[4 * c + 1], nh[4 * c + 2], nh[4 * c + 3]);
        if (out) {
            float4* Og = (float4*)&out[(size_t)u * 32];
#pragma unroll
            for (int c = 0; c < 8; c++)
                Og[c] = make_float4(nh[4 * c], nh[4 * c + 1], nh[4 * c + 2], nh[4 * c + 3]);
        }
    }

    if (write_pq) {
        const float4* Vg = (const float4*)&g_pvc[(size_t)u * 32];
        float4* Pg = (float4*)&g_P[(size_t)u * 32];
        float4* Qg = (float4*)&g_Q[(size_t)u * 32];
        for (int cb = 0; cb < 8; cb++) {
            float4 pv = Vg[cb];
            float pr[4], qr[4];
#pragma unroll
            for (int t = 0; t < 4; t++) {
                int jj = cb * 4 + t;
                const float4* wa = (const float4*)&sW1[jj * 32];
                const float4* wb = (const float4*)&sW1[(jj + 32) * 32];
                float p = 0.f, q = 0.f;
#pragma unroll
                for (int c = 0; c < 8; c++) {
                    float4 w1a = wa[c], w1b = wb[c];
                    p = fmaf(w1a.x, nh[4 * c], p);     p = fmaf(w1a.y, nh[4 * c + 1], p);
                    p = fmaf(w1a.z, nh[4 * c + 2], p); p = fmaf(w1a.w, nh[4 * c + 3], p);
                    q = fmaf(w1b.x, nh[4 * c], q);     q = fmaf(w1b.y, nh[4 * c + 1], q);
                    q = fmaf(w1b.z, nh[4 * c + 2], q); q = fmaf(w1b.w, nh[4 * c + 3], q);
                }
                pr[t] = p + sb1[jj];
                qr[t] = q;
            }
            Pg[cb] = make_float4(pr[0] - pv.x, pr[1] - pv.y, pr[2] - pv.z, pr[3] - pv.w);
            Qg[cb] = make_float4(qr[0] + pv.x, qr[1] + pv.y, qr[2] + pv.z, qr[3] + pv.w);
        }
    }
}

// ---------------- launch ----------------
extern "C" void kernel_launch(void* const* d_in, const int* in_sizes, int n_in,
                              void* d_out, int out_size) {
    const float* pos     = (const float*)d_in[0];
    const float* classes = (const float*)d_in[1];
    const int*   edges   = (const int*)d_in[2];
    int wb = (in_sizes[3] == 1) ? 4 : 3;
    const float* Win = (const float*)d_in[wb + 0];
    const float* bin = (const float*)d_in[wb + 1];
    const float* W1  = (const float*)d_in[wb + 2];
    const float* b1  = (const float*)d_in[wb + 3];
    const float* W2  = (const float*)d_in[wb + 4];
    const float* b2  = (const float*)d_in[wb + 5];
    const float* W3  = (const float*)d_in[wb + 6];
    const float* b3  = (const float*)d_in[wb + 7];
    const float* Wih = (const float*)d_in[wb + 8];
    const float* Whh = (const float*)d_in[wb + 9];
    const float* bih = (const float*)d_in[wb + 10];
    const float* bhh = (const float*)d_in[wb + 11];

    int n_nodes = in_sizes[0] / 3;
    int n_edges = in_sizes[2] / 2;
    int n2e = 2 * n_edges;
    float* out = (float*)d_out;
    int seg = (n_nodes + NB - 1) / NB;

    cudaFuncSetAttribute(edge_kernel,
                         cudaFuncAttributeMaxDynamicSharedMemorySize,
                         EDGE_SMEM_BYTES);

    int nsb = (n2e + 255) / 256;
    int neb = (n_nodes * 32 + 255) / 256;

    count_kernel<<<nsb, 256>>>(edges, n2e);
    scan_lb_kernel<<<NB + 1, 256>>>(Wih, W3, b3, n_nodes, seg);
    scatter_embed_kernel<<<nsb + neb, 256>>>(edges, n_edges, classes, pos,
                                             Win, bin, W1, b1, n_nodes, nsb);

    int gru_grid = (n_nodes + 351) / 352;
    for (int it = 0; it < 6; ++it) {
        edge_kernel<<<444, 256, EDGE_SMEM_BYTES>>>(W2, b2, n_nodes);  // launch #4: profiled
        gru_kernel<<<gru_grid, 352>>>(
            W1, b1, Whh, bih, bhh,
            (it == 5) ? out : (float*)nullptr, (it < 5) ? 1 : 0, n_nodes);
    }
}